// round 2
// baseline (speedup 1.0000x reference)
#include <cuda_runtime.h>

#define NV 100000
#define NE 1600000

// Scratch (allocation-free rule: __device__ globals)
// g_P[v*3+0] = (P0, P1, P2, P3)
// g_P[v*3+1] = (P4, P5, P6, P7)
// g_P[v*3+2] = (P8, selfMag, selfT1, selfT2)
__device__ float4 g_P[NV * 3];
// g_acc[v] = (sum_m0, sum_mv1, sum_mv2, deg)
__device__ float4 g_acc[NV];

// ---------------------------------------------------------------------------
// Kernel 1: per-vertex precompute of all dot products + zero accumulators
// ---------------------------------------------------------------------------
__global__ void precompute_kernel(const float* __restrict__ x,
                                  const float* __restrict__ w_self0,
                                  const float* __restrict__ w_n00,
                                  const float* __restrict__ w_n10,
                                  const float* __restrict__ w_self11,
                                  const float* __restrict__ w_n01,
                                  const float* __restrict__ w_n11) {
    int v = blockIdx.x * blockDim.x + threadIdx.x;
    if (v >= NV) return;
    const float* xv = x + (size_t)v * 48;

    float P0 = 0.f, P3 = 0.f, P4 = 0.f, P9 = 0.f;
#pragma unroll
    for (int i = 0; i < 16; i++) {
        float xi = xv[i];
        P0 = fmaf(xi, __ldg(&w_n00[i]), P0);
        P3 = fmaf(xi, __ldg(&w_n01[2 * i + 0]), P3);
        P4 = fmaf(xi, __ldg(&w_n01[2 * i + 1]), P4);
        P9 = fmaf(xi, __ldg(&w_self0[i]), P9);
    }

    float a0 = 0.f, b0 = 0.f, a1 = 0.f, b1 = 0.f;
    float ap = 0.f, bp = 0.f, aq = 0.f, bq = 0.f;
    float ar = 0.f, br = 0.f, as_ = 0.f, bs = 0.f;
    float t1s = 0.f, t2s = 0.f;
#pragma unroll
    for (int c = 0; c < 16; c++) {
        float a = xv[16 + 2 * c + 0];
        float b = xv[16 + 2 * c + 1];
        float w0 = __ldg(&w_n10[2 * c + 0]);
        float w1 = __ldg(&w_n10[2 * c + 1]);
        a0 = fmaf(a, w0, a0); b0 = fmaf(b, w0, b0);
        a1 = fmaf(a, w1, a1); b1 = fmaf(b, w1, b1);
        float p = __ldg(&w_n11[4 * c + 0]);
        float q = __ldg(&w_n11[4 * c + 1]);
        float r = __ldg(&w_n11[4 * c + 2]);
        float s = __ldg(&w_n11[4 * c + 3]);
        ap = fmaf(a, p, ap); bp = fmaf(b, p, bp);
        aq = fmaf(a, q, aq); bq = fmaf(b, q, bq);
        ar = fmaf(a, r, ar); br = fmaf(b, r, br);
        as_ = fmaf(a, s, as_); bs = fmaf(b, s, bs);
        float sa = __ldg(&w_self11[2 * c + 0]);
        float sb = __ldg(&w_self11[2 * c + 1]);
        t1s = fmaf(a, sa, t1s); t1s = fmaf(-b, sb, t1s);
        t2s = fmaf(b, sa, t2s); t2s = fmaf(a, sb, t2s);
    }

    g_P[v * 3 + 0] = make_float4(P0, a0 + b1, b0 - a1, P3);
    g_P[v * 3 + 1] = make_float4(P4, ap - bq, bp + aq, ar + bs);
    g_P[v * 3 + 2] = make_float4(br - as_, P9, t1s, t2s);
    g_acc[v] = make_float4(0.f, 0.f, 0.f, 0.f);
}

// ---------------------------------------------------------------------------
// Kernel 2: per-edge message + scatter (atomics into L2-resident accumulators)
// ---------------------------------------------------------------------------
__global__ void edge_kernel(const int* __restrict__ edge_index,
                            const float* __restrict__ angles,
                            const float* __restrict__ transporters) {
    int e = blockIdx.x * blockDim.x + threadIdx.x;
    if (e >= NE) return;

    int src = edge_index[e];
    int dst = edge_index[NE + e];
    float t = angles[e];
    float g = transporters[e];

    float st, ct, sg, cg;
    __sincosf(t, &st, &ct);
    __sincosf(g, &sg, &cg);
    // cos/sin(t - g)
    float cdt = fmaf(ct, cg, st * sg);
    float sdt = fmaf(st, cg, -ct * sg);
    // cos/sin(2t - g) = angle-sum of t and (t - g)
    float c2 = fmaf(ct, cdt, -st * sdt);
    float s2 = fmaf(st, cdt, ct * sdt);

    float4 p0 = g_P[src * 3 + 0];
    float4 p1 = g_P[src * 3 + 1];
    float4 p2 = g_P[src * 3 + 2];

    float m0  = p0.x + fmaf(p0.y, cdt, p0.z * sdt);
    float mv1 = fmaf(p0.w, ct, -p1.x * st) + fmaf(p1.y, cg, -p1.z * sg)
              + fmaf(p1.w, c2, p2.x * s2);
    float mv2 = fmaf(p0.w, st, p1.x * ct) + fmaf(p1.y, sg, p1.z * cg)
              + fmaf(-p2.x, c2, p1.w * s2);

    float* acc = (float*)&g_acc[dst];
    atomicAdd(acc + 0, m0);
    atomicAdd(acc + 1, mv1);
    atomicAdd(acc + 2, mv2);
    atomicAdd(acc + 3, 1.0f);
}

// ---------------------------------------------------------------------------
// Kernel 3: per-vertex finalize
// ---------------------------------------------------------------------------
__global__ void finalize_kernel(const float* __restrict__ e1,
                                const float* __restrict__ e2,
                                float* __restrict__ out) {
    int v = blockIdx.x * blockDim.x + threadIdx.x;
    if (v >= NV) return;

    float4 acc = g_acc[v];
    float inv = 1.0f / fmaxf(acc.w, 1.0f);
    float4 p2 = g_P[v * 3 + 2];

    float mag = fmaf(acc.x, inv, p2.y);
    float t1  = fmaf(acc.y, inv, p2.z);
    float t2  = fmaf(acc.z, inv, p2.w);
    float scale = 2.0f / (1.0f + expf(-mag));

    size_t base = (size_t)v * 3;
    out[base + 0] = fmaf(t1, e1[base + 0], t2 * e2[base + 0]) * scale;
    out[base + 1] = fmaf(t1, e1[base + 1], t2 * e2[base + 1]) * scale;
    out[base + 2] = fmaf(t1, e1[base + 2], t2 * e2[base + 2]) * scale;
}

extern "C" void kernel_launch(void* const* d_in, const int* in_sizes, int n_in,
                              void* d_out, int out_size) {
    const float* x            = (const float*)d_in[0];
    const int*   edge_index   = (const int*)d_in[1];
    const float* angles       = (const float*)d_in[2];
    const float* transporters = (const float*)d_in[3];
    const float* e1           = (const float*)d_in[4];
    const float* e2           = (const float*)d_in[5];
    const float* w_self0      = (const float*)d_in[6];
    const float* w_n00        = (const float*)d_in[7];
    const float* w_n10        = (const float*)d_in[8];
    const float* w_self11     = (const float*)d_in[9];
    const float* w_n01        = (const float*)d_in[10];
    const float* w_n11        = (const float*)d_in[11];
    float*       out          = (float*)d_out;

    const int TB = 256;
    precompute_kernel<<<(NV + TB - 1) / TB, TB>>>(x, w_self0, w_n00, w_n10,
                                                  w_self11, w_n01, w_n11);
    edge_kernel<<<(NE + TB - 1) / TB, TB>>>(edge_index, angles, transporters);
    finalize_kernel<<<(NV + TB - 1) / TB, TB>>>(e1, e2, out);
}

// round 3
// speedup vs baseline: 1.7129x; 1.7129x over previous
#include <cuda_runtime.h>

#define NV 100000
#define NE 1600000

// Scratch (__device__ globals; no allocation allowed).
// Edge-phase tables (hot, L2-resident, gathered by src):
__device__ float4 g_PA[NV];   // (P0, P1, P2, P3)
__device__ float4 g_PB[NV];   // (P4, P5, P6, P7)
__device__ float  g_P8[NV];   // P8
// Finalize-only per-vertex self terms:
__device__ float4 g_self[NV]; // (selfMag, selfT1, selfT2, -)
// Accumulators: (sum_m0, sum_mv1, sum_mv2, deg)
__device__ float4 g_acc[NV];

// ---------------------------------------------------------------------------
// Kernel 1: per-vertex projections. Coalesced loads via shared-memory staging.
// 128 vertices per 128-thread block; smem row padded to 49 floats
// (49 odd -> stride 16*49 mod 32 banks is odd -> conflict-free row reads).
// ---------------------------------------------------------------------------
__global__ void __launch_bounds__(128)
precompute_kernel(const float* __restrict__ x,
                  const float* __restrict__ w_self0,
                  const float* __restrict__ w_n00,
                  const float* __restrict__ w_n10,
                  const float* __restrict__ w_self11,
                  const float* __restrict__ w_n01,
                  const float* __restrict__ w_n11) {
    __shared__ float sx[128 * 49];

    int base = blockIdx.x * 128;
    int nV = NV - base; if (nV > 128) nV = 128;

    // Coalesced stage: nV*12 float4 loads spread over 128 threads.
    const float4* xv4 = (const float4*)(x + (size_t)base * 48);
    int nf4 = nV * 12;
    for (int j = threadIdx.x; j < nf4; j += 128) {
        float4 val = xv4[j];
        int row = j / 12;
        int col = (j % 12) * 4;
        float* d = &sx[row * 49 + col];
        d[0] = val.x; d[1] = val.y; d[2] = val.z; d[3] = val.w;
    }
    __syncthreads();

    int v = base + threadIdx.x;
    if (v >= NV) return;
    const float* xv = &sx[threadIdx.x * 49];

    float P0 = 0.f, P3 = 0.f, P4 = 0.f, P9 = 0.f;
#pragma unroll
    for (int i = 0; i < 16; i++) {
        float xi = xv[i];
        P0 = fmaf(xi, __ldg(&w_n00[i]), P0);
        P3 = fmaf(xi, __ldg(&w_n01[2 * i + 0]), P3);
        P4 = fmaf(xi, __ldg(&w_n01[2 * i + 1]), P4);
        P9 = fmaf(xi, __ldg(&w_self0[i]), P9);
    }

    float a0 = 0.f, b0 = 0.f, a1 = 0.f, b1 = 0.f;
    float ap = 0.f, bp = 0.f, aq = 0.f, bq = 0.f;
    float ar = 0.f, br = 0.f, as_ = 0.f, bs = 0.f;
    float t1s = 0.f, t2s = 0.f;
#pragma unroll
    for (int c = 0; c < 16; c++) {
        float a = xv[16 + 2 * c + 0];
        float b = xv[16 + 2 * c + 1];
        float w0 = __ldg(&w_n10[2 * c + 0]);
        float w1 = __ldg(&w_n10[2 * c + 1]);
        a0 = fmaf(a, w0, a0); b0 = fmaf(b, w0, b0);
        a1 = fmaf(a, w1, a1); b1 = fmaf(b, w1, b1);
        float p = __ldg(&w_n11[4 * c + 0]);
        float q = __ldg(&w_n11[4 * c + 1]);
        float r = __ldg(&w_n11[4 * c + 2]);
        float s = __ldg(&w_n11[4 * c + 3]);
        ap = fmaf(a, p, ap); bp = fmaf(b, p, bp);
        aq = fmaf(a, q, aq); bq = fmaf(b, q, bq);
        ar = fmaf(a, r, ar); br = fmaf(b, r, br);
        as_ = fmaf(a, s, as_); bs = fmaf(b, s, bs);
        float sa = __ldg(&w_self11[2 * c + 0]);
        float sb = __ldg(&w_self11[2 * c + 1]);
        t1s = fmaf(a, sa, t1s); t1s = fmaf(-b, sb, t1s);
        t2s = fmaf(b, sa, t2s); t2s = fmaf(a, sb, t2s);
    }

    g_PA[v]   = make_float4(P0, a0 + b1, b0 - a1, P3);
    g_PB[v]   = make_float4(P4, ap - bq, bp + aq, ar + bs);
    g_P8[v]   = br - as_;
    g_self[v] = make_float4(P9, t1s, t2s, 0.f);
    g_acc[v]  = make_float4(0.f, 0.f, 0.f, 0.f);
}

// ---------------------------------------------------------------------------
// Kernel 2: per-edge message + single vectorized reduction per edge.
// ---------------------------------------------------------------------------
__global__ void __launch_bounds__(256)
edge_kernel(const int* __restrict__ edge_index,
            const float* __restrict__ angles,
            const float* __restrict__ transporters) {
    int e = blockIdx.x * blockDim.x + threadIdx.x;
    if (e >= NE) return;

    int src = edge_index[e];
    int dst = edge_index[NE + e];
    float t = angles[e];
    float g = transporters[e];

    float st, ct, sg, cg;
    __sincosf(t, &st, &ct);
    __sincosf(g, &sg, &cg);
    // cos/sin(t - g)
    float cdt = fmaf(ct, cg, st * sg);
    float sdt = fmaf(st, cg, -ct * sg);
    // cos/sin(2t - g) via angle sum of t and (t - g)
    float c2 = fmaf(ct, cdt, -st * sdt);
    float s2 = fmaf(st, cdt, ct * sdt);

    float4 pa = g_PA[src];
    float4 pb = g_PB[src];
    float  p8 = g_P8[src];

    float m0  = pa.x + fmaf(pa.y, cdt, pa.z * sdt);
    float mv1 = fmaf(pa.w, ct, -pb.x * st) + fmaf(pb.y, cg, -pb.z * sg)
              + fmaf(pb.w, c2, p8 * s2);
    float mv2 = fmaf(pa.w, st, pb.x * ct) + fmaf(pb.y, sg, pb.z * cg)
              + fmaf(-p8, c2, pb.w * s2);

    // One 16B vectorized reduction (sm_90+): acc += {m0, mv1, mv2, 1}
    float4* acc = &g_acc[dst];
    asm volatile(
        "red.relaxed.gpu.global.add.v4.f32 [%0], {%1, %2, %3, %4};"
        :: "l"(acc), "f"(m0), "f"(mv1), "f"(mv2), "f"(1.0f)
        : "memory");
}

// ---------------------------------------------------------------------------
// Kernel 3: per-vertex finalize
// ---------------------------------------------------------------------------
__global__ void __launch_bounds__(256)
finalize_kernel(const float* __restrict__ e1,
                const float* __restrict__ e2,
                float* __restrict__ out) {
    int v = blockIdx.x * blockDim.x + threadIdx.x;
    if (v >= NV) return;

    float4 acc = g_acc[v];
    float inv = 1.0f / fmaxf(acc.w, 1.0f);
    float4 sf = g_self[v];

    float mag = fmaf(acc.x, inv, sf.x);
    float t1  = fmaf(acc.y, inv, sf.y);
    float t2  = fmaf(acc.z, inv, sf.z);
    float scale = 2.0f / (1.0f + expf(-mag));

    size_t base = (size_t)v * 3;
    out[base + 0] = fmaf(t1, e1[base + 0], t2 * e2[base + 0]) * scale;
    out[base + 1] = fmaf(t1, e1[base + 1], t2 * e2[base + 1]) * scale;
    out[base + 2] = fmaf(t1, e1[base + 2], t2 * e2[base + 2]) * scale;
}

extern "C" void kernel_launch(void* const* d_in, const int* in_sizes, int n_in,
                              void* d_out, int out_size) {
    const float* x            = (const float*)d_in[0];
    const int*   edge_index   = (const int*)d_in[1];
    const float* angles       = (const float*)d_in[2];
    const float* transporters = (const float*)d_in[3];
    const float* e1           = (const float*)d_in[4];
    const float* e2           = (const float*)d_in[5];
    const float* w_self0      = (const float*)d_in[6];
    const float* w_n00        = (const float*)d_in[7];
    const float* w_n10        = (const float*)d_in[8];
    const float* w_self11     = (const float*)d_in[9];
    const float* w_n01        = (const float*)d_in[10];
    const float* w_n11        = (const float*)d_in[11];
    float*       out          = (float*)d_out;

    precompute_kernel<<<(NV + 127) / 128, 128>>>(x, w_self0, w_n00, w_n10,
                                                 w_self11, w_n01, w_n11);
    edge_kernel<<<(NE + 255) / 256, 256>>>(edge_index, angles, transporters);
    finalize_kernel<<<(NV + 255) / 256, 256>>>(e1, e2, out);
}

// round 4
// speedup vs baseline: 1.7144x; 1.0009x over previous
#include <cuda_runtime.h>

#define NV 100000
#define NE 1600000

// Scratch (__device__ globals; no allocation allowed).
// Edge-phase tables (hot, L2-resident, gathered by src):
__device__ float4 g_PA[NV];   // (P0, P1, P2, P3)
__device__ float4 g_PB[NV];   // (P4, P5, P6, P7)
__device__ float  g_P8[NV];   // P8
// Finalize-only per-vertex self terms:
__device__ float4 g_self[NV]; // (selfMag, selfT1, selfT2, -)
// Accumulators: (sum_m0, sum_mv1, sum_mv2, deg)
__device__ float4 g_acc[NV];

// ---------------------------------------------------------------------------
// Kernel 1: per-vertex projections. Coalesced loads via shared-memory staging.
// 128 vertices per 128-thread block; smem row padded to 49 floats
// (49 odd -> stride 16*49 mod 32 banks is odd -> conflict-free row reads).
// ---------------------------------------------------------------------------
__global__ void __launch_bounds__(128)
precompute_kernel(const float* __restrict__ x,
                  const float* __restrict__ w_self0,
                  const float* __restrict__ w_n00,
                  const float* __restrict__ w_n10,
                  const float* __restrict__ w_self11,
                  const float* __restrict__ w_n01,
                  const float* __restrict__ w_n11) {
    __shared__ float sx[128 * 49];

    int base = blockIdx.x * 128;
    int nV = NV - base; if (nV > 128) nV = 128;

    // Coalesced stage: nV*12 float4 loads spread over 128 threads.
    const float4* xv4 = (const float4*)(x + (size_t)base * 48);
    int nf4 = nV * 12;
    for (int j = threadIdx.x; j < nf4; j += 128) {
        float4 val = xv4[j];
        int row = j / 12;
        int col = (j % 12) * 4;
        float* d = &sx[row * 49 + col];
        d[0] = val.x; d[1] = val.y; d[2] = val.z; d[3] = val.w;
    }
    __syncthreads();

    int v = base + threadIdx.x;
    if (v >= NV) return;
    const float* xv = &sx[threadIdx.x * 49];

    float P0 = 0.f, P3 = 0.f, P4 = 0.f, P9 = 0.f;
#pragma unroll
    for (int i = 0; i < 16; i++) {
        float xi = xv[i];
        P0 = fmaf(xi, __ldg(&w_n00[i]), P0);
        P3 = fmaf(xi, __ldg(&w_n01[2 * i + 0]), P3);
        P4 = fmaf(xi, __ldg(&w_n01[2 * i + 1]), P4);
        P9 = fmaf(xi, __ldg(&w_self0[i]), P9);
    }

    float a0 = 0.f, b0 = 0.f, a1 = 0.f, b1 = 0.f;
    float ap = 0.f, bp = 0.f, aq = 0.f, bq = 0.f;
    float ar = 0.f, br = 0.f, as_ = 0.f, bs = 0.f;
    float t1s = 0.f, t2s = 0.f;
#pragma unroll
    for (int c = 0; c < 16; c++) {
        float a = xv[16 + 2 * c + 0];
        float b = xv[16 + 2 * c + 1];
        float w0 = __ldg(&w_n10[2 * c + 0]);
        float w1 = __ldg(&w_n10[2 * c + 1]);
        a0 = fmaf(a, w0, a0); b0 = fmaf(b, w0, b0);
        a1 = fmaf(a, w1, a1); b1 = fmaf(b, w1, b1);
        float p = __ldg(&w_n11[4 * c + 0]);
        float q = __ldg(&w_n11[4 * c + 1]);
        float r = __ldg(&w_n11[4 * c + 2]);
        float s = __ldg(&w_n11[4 * c + 3]);
        ap = fmaf(a, p, ap); bp = fmaf(b, p, bp);
        aq = fmaf(a, q, aq); bq = fmaf(b, q, bq);
        ar = fmaf(a, r, ar); br = fmaf(b, r, br);
        as_ = fmaf(a, s, as_); bs = fmaf(b, s, bs);
        float sa = __ldg(&w_self11[2 * c + 0]);
        float sb = __ldg(&w_self11[2 * c + 1]);
        t1s = fmaf(a, sa, t1s); t1s = fmaf(-b, sb, t1s);
        t2s = fmaf(b, sa, t2s); t2s = fmaf(a, sb, t2s);
    }

    g_PA[v]   = make_float4(P0, a0 + b1, b0 - a1, P3);
    g_PB[v]   = make_float4(P4, ap - bq, bp + aq, ar + bs);
    g_P8[v]   = br - as_;
    g_self[v] = make_float4(P9, t1s, t2s, 0.f);
    g_acc[v]  = make_float4(0.f, 0.f, 0.f, 0.f);
}

// ---------------------------------------------------------------------------
// Kernel 2: per-edge message + single vectorized reduction per edge.
// ---------------------------------------------------------------------------
__global__ void __launch_bounds__(256)
edge_kernel(const int* __restrict__ edge_index,
            const float* __restrict__ angles,
            const float* __restrict__ transporters) {
    int e = blockIdx.x * blockDim.x + threadIdx.x;
    if (e >= NE) return;

    int src = edge_index[e];
    int dst = edge_index[NE + e];
    float t = angles[e];
    float g = transporters[e];

    float st, ct, sg, cg;
    __sincosf(t, &st, &ct);
    __sincosf(g, &sg, &cg);
    // cos/sin(t - g)
    float cdt = fmaf(ct, cg, st * sg);
    float sdt = fmaf(st, cg, -ct * sg);
    // cos/sin(2t - g) via angle sum of t and (t - g)
    float c2 = fmaf(ct, cdt, -st * sdt);
    float s2 = fmaf(st, cdt, ct * sdt);

    float4 pa = g_PA[src];
    float4 pb = g_PB[src];
    float  p8 = g_P8[src];

    float m0  = pa.x + fmaf(pa.y, cdt, pa.z * sdt);
    float mv1 = fmaf(pa.w, ct, -pb.x * st) + fmaf(pb.y, cg, -pb.z * sg)
              + fmaf(pb.w, c2, p8 * s2);
    float mv2 = fmaf(pa.w, st, pb.x * ct) + fmaf(pb.y, sg, pb.z * cg)
              + fmaf(-p8, c2, pb.w * s2);

    // One 16B vectorized reduction (sm_90+): acc += {m0, mv1, mv2, 1}
    float4* acc = &g_acc[dst];
    asm volatile(
        "red.relaxed.gpu.global.add.v4.f32 [%0], {%1, %2, %3, %4};"
        :: "l"(acc), "f"(m0), "f"(mv1), "f"(mv2), "f"(1.0f)
        : "memory");
}

// ---------------------------------------------------------------------------
// Kernel 3: per-vertex finalize
// ---------------------------------------------------------------------------
__global__ void __launch_bounds__(256)
finalize_kernel(const float* __restrict__ e1,
                const float* __restrict__ e2,
                float* __restrict__ out) {
    int v = blockIdx.x * blockDim.x + threadIdx.x;
    if (v >= NV) return;

    float4 acc = g_acc[v];
    float inv = 1.0f / fmaxf(acc.w, 1.0f);
    float4 sf = g_self[v];

    float mag = fmaf(acc.x, inv, sf.x);
    float t1  = fmaf(acc.y, inv, sf.y);
    float t2  = fmaf(acc.z, inv, sf.z);
    float scale = 2.0f / (1.0f + expf(-mag));

    size_t base = (size_t)v * 3;
    out[base + 0] = fmaf(t1, e1[base + 0], t2 * e2[base + 0]) * scale;
    out[base + 1] = fmaf(t1, e1[base + 1], t2 * e2[base + 1]) * scale;
    out[base + 2] = fmaf(t1, e1[base + 2], t2 * e2[base + 2]) * scale;
}

extern "C" void kernel_launch(void* const* d_in, const int* in_sizes, int n_in,
                              void* d_out, int out_size) {
    const float* x            = (const float*)d_in[0];
    const int*   edge_index   = (const int*)d_in[1];
    const float* angles       = (const float*)d_in[2];
    const float* transporters = (const float*)d_in[3];
    const float* e1           = (const float*)d_in[4];
    const float* e2           = (const float*)d_in[5];
    const float* w_self0      = (const float*)d_in[6];
    const float* w_n00        = (const float*)d_in[7];
    const float* w_n10        = (const float*)d_in[8];
    const float* w_self11     = (const float*)d_in[9];
    const float* w_n01        = (const float*)d_in[10];
    const float* w_n11        = (const float*)d_in[11];
    float*       out          = (float*)d_out;

    precompute_kernel<<<(NV + 127) / 128, 128>>>(x, w_self0, w_n00, w_n10,
                                                 w_self11, w_n01, w_n11);
    edge_kernel<<<(NE + 255) / 256, 256>>>(edge_index, angles, transporters);
    finalize_kernel<<<(NV + 255) / 256, 256>>>(e1, e2, out);
}

// round 5
// speedup vs baseline: 1.7977x; 1.0486x over previous
#include <cuda_runtime.h>

#define NV 100000
#define NE 1600000
#define PREF_BLOCKS 256
#define VERT_BLOCKS ((NV + 127) / 128)

// Packed per-vertex projection record: 9 hot floats in one 64B-aligned slot
// -> any random gather touches exactly 2 L2 sectors (64B).
struct __align__(64) PRec {
    float4 a;      // (P0, P1, P2, P3)
    float4 b;      // (P4, P5, P6, P7)
    float  p8;     // P8
    float  pad[3];
};

__device__ PRec   g_P[NV];
__device__ float4 g_self[NV]; // (selfMag, selfT1, selfT2, -)
__device__ float4 g_acc[NV];  // (sum_m0, sum_mv1, sum_mv2, deg)

__device__ __forceinline__ void l2_prefetch(const char* p) {
    asm volatile("prefetch.global.L2 [%0];" :: "l"(p));
}

// ---------------------------------------------------------------------------
// Kernel 1: per-vertex projections (coalesced via smem staging) PLUS
// trailing blocks that prefetch the edge-phase streams into L2 while the
// vertex math (latency-bound, DRAM 21% busy) runs.
// ---------------------------------------------------------------------------
__global__ void __launch_bounds__(128)
precompute_kernel(const float* __restrict__ x,
                  const float* __restrict__ w_self0,
                  const float* __restrict__ w_n00,
                  const float* __restrict__ w_n10,
                  const float* __restrict__ w_self11,
                  const float* __restrict__ w_n01,
                  const float* __restrict__ w_n11,
                  const char* __restrict__ edge_index,
                  const char* __restrict__ angles,
                  const char* __restrict__ transporters,
                  const char* __restrict__ e1,
                  const char* __restrict__ e2) {
    if (blockIdx.x >= VERT_BLOCKS) {
        // ---- prefetch blocks: warm L2 with the edge/finalize streams ----
        long long tid = (long long)(blockIdx.x - VERT_BLOCKS) * 128 + threadIdx.x;
        long long nthr = (long long)PREF_BLOCKS * 128;
        // edge_index: 2*NE int32 = 12.8MB; angles/transporters: 6.4MB each;
        // e1/e2: 1.2MB each.
        for (long long o = tid * 128; o < (long long)2 * NE * 4; o += nthr * 128)
            l2_prefetch(edge_index + o);
        for (long long o = tid * 128; o < (long long)NE * 4; o += nthr * 128) {
            l2_prefetch(angles + o);
            l2_prefetch(transporters + o);
        }
        for (long long o = tid * 128; o < (long long)NV * 12; o += nthr * 128) {
            l2_prefetch(e1 + o);
            l2_prefetch(e2 + o);
        }
        return;
    }

    __shared__ float sx[128 * 49];

    int base = blockIdx.x * 128;
    int nV = NV - base; if (nV > 128) nV = 128;

    const float4* xv4 = (const float4*)(x + (size_t)base * 48);
    int nf4 = nV * 12;
    for (int j = threadIdx.x; j < nf4; j += 128) {
        float4 val = xv4[j];
        int row = j / 12;
        int col = (j % 12) * 4;
        float* d = &sx[row * 49 + col];
        d[0] = val.x; d[1] = val.y; d[2] = val.z; d[3] = val.w;
    }
    __syncthreads();

    int v = base + threadIdx.x;
    if (v >= NV) return;
    const float* xv = &sx[threadIdx.x * 49];

    float P0 = 0.f, P3 = 0.f, P4 = 0.f, P9 = 0.f;
#pragma unroll
    for (int i = 0; i < 16; i++) {
        float xi = xv[i];
        P0 = fmaf(xi, __ldg(&w_n00[i]), P0);
        P3 = fmaf(xi, __ldg(&w_n01[2 * i + 0]), P3);
        P4 = fmaf(xi, __ldg(&w_n01[2 * i + 1]), P4);
        P9 = fmaf(xi, __ldg(&w_self0[i]), P9);
    }

    float a0 = 0.f, b0 = 0.f, a1 = 0.f, b1 = 0.f;
    float ap = 0.f, bp = 0.f, aq = 0.f, bq = 0.f;
    float ar = 0.f, br = 0.f, as_ = 0.f, bs = 0.f;
    float t1s = 0.f, t2s = 0.f;
#pragma unroll
    for (int c = 0; c < 16; c++) {
        float a = xv[16 + 2 * c + 0];
        float b = xv[16 + 2 * c + 1];
        float w0 = __ldg(&w_n10[2 * c + 0]);
        float w1 = __ldg(&w_n10[2 * c + 1]);
        a0 = fmaf(a, w0, a0); b0 = fmaf(b, w0, b0);
        a1 = fmaf(a, w1, a1); b1 = fmaf(b, w1, b1);
        float p = __ldg(&w_n11[4 * c + 0]);
        float q = __ldg(&w_n11[4 * c + 1]);
        float r = __ldg(&w_n11[4 * c + 2]);
        float s = __ldg(&w_n11[4 * c + 3]);
        ap = fmaf(a, p, ap); bp = fmaf(b, p, bp);
        aq = fmaf(a, q, aq); bq = fmaf(b, q, bq);
        ar = fmaf(a, r, ar); br = fmaf(b, r, br);
        as_ = fmaf(a, s, as_); bs = fmaf(b, s, bs);
        float sa = __ldg(&w_self11[2 * c + 0]);
        float sb = __ldg(&w_self11[2 * c + 1]);
        t1s = fmaf(a, sa, t1s); t1s = fmaf(-b, sb, t1s);
        t2s = fmaf(b, sa, t2s); t2s = fmaf(a, sb, t2s);
    }

    PRec rec;
    rec.a = make_float4(P0, a0 + b1, b0 - a1, P3);
    rec.b = make_float4(P4, ap - bq, bp + aq, ar + bs);
    rec.p8 = br - as_;
    rec.pad[0] = rec.pad[1] = rec.pad[2] = 0.f;
    g_P[v] = rec;
    g_self[v] = make_float4(P9, t1s, t2s, 0.f);
    g_acc[v]  = make_float4(0.f, 0.f, 0.f, 0.f);
}

// ---------------------------------------------------------------------------
// Kernel 2: 2 edges per thread; vectorized stream loads; one v4 RED per edge.
// ---------------------------------------------------------------------------
__device__ __forceinline__ void edge_msg(int src, float t, float g,
                                         float& m0, float& mv1, float& mv2) {
    float st, ct, sg, cg;
    __sincosf(t, &st, &ct);
    __sincosf(g, &sg, &cg);
    float cdt = fmaf(ct, cg, st * sg);     // cos(t-g)
    float sdt = fmaf(st, cg, -ct * sg);    // sin(t-g)
    float c2 = fmaf(ct, cdt, -st * sdt);   // cos(2t-g)
    float s2 = fmaf(st, cdt, ct * sdt);    // sin(2t-g)

    const PRec& pr = g_P[src];
    float4 pa = pr.a;
    float4 pb = pr.b;
    float  p8 = pr.p8;

    m0  = pa.x + fmaf(pa.y, cdt, pa.z * sdt);
    mv1 = fmaf(pa.w, ct, -pb.x * st) + fmaf(pb.y, cg, -pb.z * sg)
        + fmaf(pb.w, c2, p8 * s2);
    mv2 = fmaf(pa.w, st, pb.x * ct) + fmaf(pb.y, sg, pb.z * cg)
        + fmaf(-p8, c2, pb.w * s2);
}

__global__ void __launch_bounds__(256)
edge_kernel(const int* __restrict__ edge_index,
            const float* __restrict__ angles,
            const float* __restrict__ transporters) {
    int i = blockIdx.x * blockDim.x + threadIdx.x;   // pair index
    if (i >= NE / 2) return;

    int2   s2i = ((const int2*)edge_index)[i];
    int2   d2i = ((const int2*)(edge_index + NE))[i];
    float2 tt  = ((const float2*)angles)[i];
    float2 gg  = ((const float2*)transporters)[i];

    float m0a, mv1a, mv2a, m0b, mv1b, mv2b;
    edge_msg(s2i.x, tt.x, gg.x, m0a, mv1a, mv2a);
    edge_msg(s2i.y, tt.y, gg.y, m0b, mv1b, mv2b);

    asm volatile("red.relaxed.gpu.global.add.v4.f32 [%0], {%1, %2, %3, %4};"
                 :: "l"(&g_acc[d2i.x]), "f"(m0a), "f"(mv1a), "f"(mv2a), "f"(1.0f)
                 : "memory");
    asm volatile("red.relaxed.gpu.global.add.v4.f32 [%0], {%1, %2, %3, %4};"
                 :: "l"(&g_acc[d2i.y]), "f"(m0b), "f"(mv1b), "f"(mv2b), "f"(1.0f)
                 : "memory");
}

// ---------------------------------------------------------------------------
// Kernel 3: per-vertex finalize
// ---------------------------------------------------------------------------
__global__ void __launch_bounds__(256)
finalize_kernel(const float* __restrict__ e1,
                const float* __restrict__ e2,
                float* __restrict__ out) {
    int v = blockIdx.x * blockDim.x + threadIdx.x;
    if (v >= NV) return;

    float4 acc = g_acc[v];
    float inv = 1.0f / fmaxf(acc.w, 1.0f);
    float4 sf = g_self[v];

    float mag = fmaf(acc.x, inv, sf.x);
    float t1  = fmaf(acc.y, inv, sf.y);
    float t2  = fmaf(acc.z, inv, sf.z);
    float scale = 2.0f / (1.0f + expf(-mag));

    size_t base = (size_t)v * 3;
    out[base + 0] = fmaf(t1, e1[base + 0], t2 * e2[base + 0]) * scale;
    out[base + 1] = fmaf(t1, e1[base + 1], t2 * e2[base + 1]) * scale;
    out[base + 2] = fmaf(t1, e1[base + 2], t2 * e2[base + 2]) * scale;
}

extern "C" void kernel_launch(void* const* d_in, const int* in_sizes, int n_in,
                              void* d_out, int out_size) {
    const float* x            = (const float*)d_in[0];
    const int*   edge_index   = (const int*)d_in[1];
    const float* angles       = (const float*)d_in[2];
    const float* transporters = (const float*)d_in[3];
    const float* e1           = (const float*)d_in[4];
    const float* e2           = (const float*)d_in[5];
    const float* w_self0      = (const float*)d_in[6];
    const float* w_n00        = (const float*)d_in[7];
    const float* w_n10        = (const float*)d_in[8];
    const float* w_self11     = (const float*)d_in[9];
    const float* w_n01        = (const float*)d_in[10];
    const float* w_n11        = (const float*)d_in[11];
    float*       out          = (float*)d_out;

    precompute_kernel<<<VERT_BLOCKS + PREF_BLOCKS, 128>>>(
        x, w_self0, w_n00, w_n10, w_self11, w_n01, w_n11,
        (const char*)edge_index, (const char*)angles, (const char*)transporters,
        (const char*)e1, (const char*)e2);
    edge_kernel<<<(NE / 2 + 255) / 256, 256>>>(edge_index, angles, transporters);
    finalize_kernel<<<(NV + 255) / 256, 256>>>(e1, e2, out);
}

// round 6
// speedup vs baseline: 2.1943x; 1.2206x over previous
#include <cuda_runtime.h>
#include <cuda_fp16.h>

#define NV 100000
#define NE 1600000
#define VERT_BLOCKS ((NV + 127) / 128)

// Packed per-vertex projection record: one 32B L2 sector per gather.
//   w.x  = P0 (fp32)
//   w.y  = half2(P1, P2)
//   w.z  = half2(P3, P4)
//   w.w  = half2(P5, P6)
//   w4   = half2(P7, P8)
struct __align__(32) PRec16 {
    uint4 w;
    unsigned int w4;
    unsigned int pad[3];
};

__device__ PRec16 g_P16[NV];
__device__ float4 g_self[NV]; // (selfMag, selfT1, selfT2, -)
__device__ float4 g_acc[NV];  // (sum_m0, sum_mv1, sum_mv2, deg)

__device__ __forceinline__ void l2_prefetch(const char* p) {
    asm volatile("prefetch.global.L2 [%0];" :: "l"(p));
}
__device__ __forceinline__ unsigned int pack2(float a, float b) {
    __half2 h = __floats2half2_rn(a, b);
    return *(unsigned int*)&h;
}

// ---------------------------------------------------------------------------
// Kernel 1: per-vertex projections (coalesced via smem staging). Each thread
// first fires ≤3 L2 prefetches covering the edge streams (fire-and-forget,
// overlaps the latency-bound vertex math; no extra blocks, no kernel tail).
// ---------------------------------------------------------------------------
__global__ void __launch_bounds__(128)
precompute_kernel(const float* __restrict__ x,
                  const float* __restrict__ w_self0,
                  const float* __restrict__ w_n00,
                  const float* __restrict__ w_n10,
                  const float* __restrict__ w_self11,
                  const float* __restrict__ w_n01,
                  const float* __restrict__ w_n11,
                  const char* __restrict__ edge_index,
                  const char* __restrict__ angles,
                  const char* __restrict__ transporters) {
    int base = blockIdx.x * 128;
    int tid  = base + threadIdx.x;

    // Warm L2 with the edge streams: edge_index 12.8MB = 100000 lines of 128B,
    // angles 6.4MB = 50000 lines, transporters 6.4MB = 50000 lines.
    if (tid < 100000) {
        l2_prefetch(edge_index + (size_t)tid * 128);
        if (tid < 50000) {
            l2_prefetch(angles + (size_t)tid * 128);
            l2_prefetch(transporters + (size_t)tid * 128);
        } else {
            l2_prefetch(angles + (size_t)(tid - 50000) * 128 + 6400000);
            l2_prefetch(transporters + (size_t)(tid - 50000) * 128 + 6400000);
        }
    }

    __shared__ float sx[128 * 49];

    int nV = NV - base; if (nV > 128) nV = 128;
    const float4* xv4 = (const float4*)(x + (size_t)base * 48);
    int nf4 = nV * 12;
    for (int j = threadIdx.x; j < nf4; j += 128) {
        float4 val = xv4[j];
        int row = j / 12;
        int col = (j % 12) * 4;
        float* d = &sx[row * 49 + col];
        d[0] = val.x; d[1] = val.y; d[2] = val.z; d[3] = val.w;
    }
    __syncthreads();

    int v = tid;
    if (v >= NV) return;
    const float* xv = &sx[threadIdx.x * 49];

    float P0 = 0.f, P3 = 0.f, P4 = 0.f, P9 = 0.f;
#pragma unroll
    for (int i = 0; i < 16; i++) {
        float xi = xv[i];
        P0 = fmaf(xi, __ldg(&w_n00[i]), P0);
        P3 = fmaf(xi, __ldg(&w_n01[2 * i + 0]), P3);
        P4 = fmaf(xi, __ldg(&w_n01[2 * i + 1]), P4);
        P9 = fmaf(xi, __ldg(&w_self0[i]), P9);
    }

    float a0 = 0.f, b0 = 0.f, a1 = 0.f, b1 = 0.f;
    float ap = 0.f, bp = 0.f, aq = 0.f, bq = 0.f;
    float ar = 0.f, br = 0.f, as_ = 0.f, bs = 0.f;
    float t1s = 0.f, t2s = 0.f;
#pragma unroll
    for (int c = 0; c < 16; c++) {
        float a = xv[16 + 2 * c + 0];
        float b = xv[16 + 2 * c + 1];
        float w0 = __ldg(&w_n10[2 * c + 0]);
        float w1 = __ldg(&w_n10[2 * c + 1]);
        a0 = fmaf(a, w0, a0); b0 = fmaf(b, w0, b0);
        a1 = fmaf(a, w1, a1); b1 = fmaf(b, w1, b1);
        float p = __ldg(&w_n11[4 * c + 0]);
        float q = __ldg(&w_n11[4 * c + 1]);
        float r = __ldg(&w_n11[4 * c + 2]);
        float s = __ldg(&w_n11[4 * c + 3]);
        ap = fmaf(a, p, ap); bp = fmaf(b, p, bp);
        aq = fmaf(a, q, aq); bq = fmaf(b, q, bq);
        ar = fmaf(a, r, ar); br = fmaf(b, r, br);
        as_ = fmaf(a, s, as_); bs = fmaf(b, s, bs);
        float sa = __ldg(&w_self11[2 * c + 0]);
        float sb = __ldg(&w_self11[2 * c + 1]);
        t1s = fmaf(a, sa, t1s); t1s = fmaf(-b, sb, t1s);
        t2s = fmaf(b, sa, t2s); t2s = fmaf(a, sb, t2s);
    }

    PRec16 rec;
    rec.w = make_uint4(__float_as_uint(P0),
                       pack2(a0 + b1, b0 - a1),     // (P1, P2)
                       pack2(P3, P4),               // (P3, P4)
                       pack2(ap - bq, bp + aq));    // (P5, P6)
    rec.w4 = pack2(ar + bs, br - as_);              // (P7, P8)
    rec.pad[0] = rec.pad[1] = rec.pad[2] = 0u;
    g_P16[v] = rec;
    g_self[v] = make_float4(P9, t1s, t2s, 0.f);
    g_acc[v]  = make_float4(0.f, 0.f, 0.f, 0.f);
}

// ---------------------------------------------------------------------------
// Kernel 2: 4 edges per thread; single-sector fp16 gather; one v4 RED/edge.
// ---------------------------------------------------------------------------
__device__ __forceinline__ void edge_msg(int src, float t, float g,
                                         float& m0, float& mv1, float& mv2) {
    float st, ct, sg, cg;
    __sincosf(t, &st, &ct);
    __sincosf(g, &sg, &cg);
    float cdt = fmaf(ct, cg, st * sg);     // cos(t-g)
    float sdt = fmaf(st, cg, -ct * sg);    // sin(t-g)
    float c2 = fmaf(ct, cdt, -st * sdt);   // cos(2t-g)
    float s2 = fmaf(st, cdt, ct * sdt);    // sin(2t-g)

    const PRec16& pr = g_P16[src];
    uint4 w = pr.w;
    unsigned int w4 = pr.w4;
    float  p0  = __uint_as_float(w.x);
    float2 p12 = __half22float2(*(const __half2*)&w.y);
    float2 p34 = __half22float2(*(const __half2*)&w.z);
    float2 p56 = __half22float2(*(const __half2*)&w.w);
    float2 p78 = __half22float2(*(const __half2*)&w4);

    m0  = p0 + fmaf(p12.x, cdt, p12.y * sdt);
    mv1 = fmaf(p34.x, ct, -p34.y * st) + fmaf(p56.x, cg, -p56.y * sg)
        + fmaf(p78.x, c2, p78.y * s2);
    mv2 = fmaf(p34.x, st, p34.y * ct) + fmaf(p56.x, sg, p56.y * cg)
        + fmaf(-p78.y, c2, p78.x * s2);
}

__global__ void __launch_bounds__(256)
edge_kernel(const int* __restrict__ edge_index,
            const float* __restrict__ angles,
            const float* __restrict__ transporters) {
    int i = blockIdx.x * blockDim.x + threadIdx.x;   // quad index
    if (i >= NE / 4) return;

    int4   s4 = ((const int4*)edge_index)[i];
    int4   d4 = ((const int4*)(edge_index + NE))[i];
    float4 t4 = ((const float4*)angles)[i];
    float4 g4 = ((const float4*)transporters)[i];

    float m0, mv1, mv2;
#define DO_EDGE(SRC, DST, T, G)                                              \
    edge_msg(SRC, T, G, m0, mv1, mv2);                                       \
    asm volatile("red.relaxed.gpu.global.add.v4.f32 [%0], {%1, %2, %3, %4};" \
                 :: "l"(&g_acc[DST]), "f"(m0), "f"(mv1), "f"(mv2), "f"(1.0f) \
                 : "memory");

    DO_EDGE(s4.x, d4.x, t4.x, g4.x)
    DO_EDGE(s4.y, d4.y, t4.y, g4.y)
    DO_EDGE(s4.z, d4.z, t4.z, g4.z)
    DO_EDGE(s4.w, d4.w, t4.w, g4.w)
#undef DO_EDGE
}

// ---------------------------------------------------------------------------
// Kernel 3: per-vertex finalize
// ---------------------------------------------------------------------------
__global__ void __launch_bounds__(256)
finalize_kernel(const float* __restrict__ e1,
                const float* __restrict__ e2,
                float* __restrict__ out) {
    int v = blockIdx.x * blockDim.x + threadIdx.x;
    if (v >= NV) return;

    float4 acc = g_acc[v];
    float inv = 1.0f / fmaxf(acc.w, 1.0f);
    float4 sf = g_self[v];

    float mag = fmaf(acc.x, inv, sf.x);
    float t1  = fmaf(acc.y, inv, sf.y);
    float t2  = fmaf(acc.z, inv, sf.z);
    float scale = 2.0f / (1.0f + expf(-mag));

    size_t base = (size_t)v * 3;
    out[base + 0] = fmaf(t1, e1[base + 0], t2 * e2[base + 0]) * scale;
    out[base + 1] = fmaf(t1, e1[base + 1], t2 * e2[base + 1]) * scale;
    out[base + 2] = fmaf(t1, e1[base + 2], t2 * e2[base + 2]) * scale;
}

extern "C" void kernel_launch(void* const* d_in, const int* in_sizes, int n_in,
                              void* d_out, int out_size) {
    const float* x            = (const float*)d_in[0];
    const int*   edge_index   = (const int*)d_in[1];
    const float* angles       = (const float*)d_in[2];
    const float* transporters = (const float*)d_in[3];
    const float* e1           = (const float*)d_in[4];
    const float* e2           = (const float*)d_in[5];
    const float* w_self0      = (const float*)d_in[6];
    const float* w_n00        = (const float*)d_in[7];
    const float* w_n10        = (const float*)d_in[8];
    const float* w_self11     = (const float*)d_in[9];
    const float* w_n01        = (const float*)d_in[10];
    const float* w_n11        = (const float*)d_in[11];
    float*       out          = (float*)d_out;

    precompute_kernel<<<VERT_BLOCKS, 128>>>(
        x, w_self0, w_n00, w_n10, w_self11, w_n01, w_n11,
        (const char*)edge_index, (const char*)angles, (const char*)transporters);
    edge_kernel<<<(NE / 4 + 255) / 256, 256>>>(edge_index, angles, transporters);
    finalize_kernel<<<(NV + 255) / 256, 256>>>(e1, e2, out);
}